// round 10
// baseline (speedup 1.0000x reference)
#include <cuda_runtime.h>
#include <cstdint>
#include <math.h>

// Problem constants
#define BATCH   8192
#define NNODES  32
#define DIN     128
#define HID     128
#define TT      3

// Scratch (__device__ globals; cudaMalloc is forbidden)
__device__ float g_C[BATCH * TT * DIN];   // combined vectors (b, j*128+d)
__device__ float g_u[9 * DIN];            // u[i*3+j][d] = sum_h W[i][d][h]*a_top[j][h]
__device__ float g_v[TT * DIN];           // v[j][d]     = sum_h W[j][d][h]*a_bot[j][h]
__device__ unsigned g_det;                // mask dtype bits (atomicOr; idempotent across replays)
__device__ unsigned g_done;               // producer completion flag (reset by k2)

#define FLAG_TARGET 385u                  // 384 dot-warps + 1 detection-warp

// ---------------------------------------------------------------------------
// Mask dtype helpers (bool buffer may be u8 / i32 / f32 on device).
// ---------------------------------------------------------------------------
__device__ __forceinline__ int mask_mode_from_det(unsigned d)
{
    if (!(d & 1u)) return 1;   // int32
    if (!(d & 2u)) return 2;   // float32
    return 0;                  // uint8
}
__device__ __forceinline__ bool mask_at(const void* m, size_t idx, int mode)
{
    if (mode == 0) return ((const unsigned char*)m)[idx] != 0;
    if (mode == 1) return ((const int*)m)[idx] != 0;
    return ((const float*)m)[idx] != 0.f;
}

__device__ __forceinline__ float dot4(float4 x, float4 y)
{ return x.x * y.x + x.y * y.y + x.z * y.z + x.w * y.w; }

// ---------------------------------------------------------------------------
// k1 (fused): CTAs 0..47 first produce u/v (4 dots per warp) + detection,
// then everyone processes one batch per warp. Consumers prefetch their h
// tile to L2 while the producers finish (spin on g_done, nanosleep-yield).
// 8 warps/CTA, grid=1024, __launch_bounds__(256,4) -> 32 warps/SM.
// ---------------------------------------------------------------------------
#define K1_WARPS 8
#define WSL      224   // per-warp smem floats: nb[3][32] + ss[16] + wt[3][32] + pad

__global__ __launch_bounds__(256, 4) void k1_fused(
    const float* __restrict__ h, const void* __restrict__ mask,
    const float* __restrict__ W, const float* __restrict__ a)
{
    __shared__ float smem[K1_WARPS * WSL];
    const int lane = threadIdx.x & 31;
    const int w    = threadIdx.x >> 5;
    const int cta  = blockIdx.x;
    const int b    = cta * K1_WARPS + w;

    const float* hb = h + (size_t)b * NNODES * DIN;

    // ================= producer phase (CTAs 0..47) =================
    if (cta < 48) {
        const int wg   = cta * 8 + w;        // 0..383
        const int base = wg * 4;             // dot ids base..base+3
        const int vb   = base >> 7;          // 0..11
        const int d0   = base & 127;

        const float* Wbase;
        const float* avec;
        if (vb < 9) {
            Wbase = W + (size_t)(vb / 3) * (DIN * HID);
            avec  = a + (vb % 3) * (2 * HID);
        } else {
            Wbase = W + (size_t)(vb - 9) * (DIN * HID);
            avec  = a + (vb - 9) * (2 * HID) + HID;
        }
        float4 av = *(const float4*)&avec[lane << 2];
        float acc[4];
        #pragma unroll
        for (int r = 0; r < 4; ++r) {
            float4 wv = *(const float4*)&Wbase[(size_t)(d0 + r) * HID + (lane << 2)];
            acc[r] = dot4(wv, av);
        }
        #pragma unroll
        for (int o = 16; o; o >>= 1)
            #pragma unroll
            for (int r = 0; r < 4; ++r)
                acc[r] += __shfl_xor_sync(0xffffffffu, acc[r], o);
        if (lane == 0) {
            float4 res = {acc[0], acc[1], acc[2], acc[3]};
            if (vb < 9) *(float4*)&g_u[vb * DIN + d0] = res;
            else        *(float4*)&g_v[(vb - 9) * DIN + d0] = res;
        }
        __threadfence();
        if (lane == 0) atomicAdd(&g_done, 1u);

        if (wg == 0) {   // detection warp: scan first 8KB (2048 words)
            const unsigned* mraw = (const unsigned*)mask;
            unsigned local = 0;
            for (int i = lane; i < 2048; i += 32) {
                unsigned ww = mraw[i];
                if (ww > 1u) local |= 1u;
                if (ww != 0u && ww != 0x3F800000u) local |= 2u;
            }
            #pragma unroll
            for (int o = 16; o; o >>= 1) local |= __shfl_xor_sync(0xffffffffu, local, o);
            if (lane == 0) {
                if (local) atomicOr(&g_det, local);
                __threadfence();
                atomicAdd(&g_done, 1u);
            }
        }
    } else {
        // consumers: prefetch our 16KB h tile + mask lines to L2 before spinning
        const char* hp = (const char*)hb;
        #pragma unroll
        for (int i = 0; i < 4; ++i)
            asm volatile("prefetch.global.L2 [%0];" :: "l"(hp + (lane + i * 32) * 128));
    }

    // ================= wait for producers =================
    if (lane == 0) {
        volatile unsigned* vp = (volatile unsigned*)&g_done;
        while (*vp < FLAG_TARGET) __nanosleep(64);
    }
    __syncwarp();
    __threadfence();   // acquire: order g_u/g_v/g_det loads after flag

    const int mode = mask_mode_from_det(g_det);
    float* snb = smem + w * WSL;     // [3][32] neighbor scores
    float* sss = snb + 96;           // [9] self scores (+pad)
    float* swt = sss + 16;           // [3][32] weights

    const int g = lane >> 3;         // group 0..3 (node within 4-pack)
    const int q = lane & 7;          // quarter position 0..7

    // ---- masks for this lane's node ----
    const size_t mstr = (size_t)BATCH * NNODES;
    const size_t mb   = (size_t)b * NNODES + lane;
    const bool m0 = mask_at(mask, 0 * mstr + mb, mode);
    const bool m1 = mask_at(mask, 1 * mstr + mb, mode);
    const bool m2 = mask_at(mask, 2 * mstr + mb, mode);

    // ---- dot phase: 8 iterations x 4 nodes ----
    #pragma unroll
    for (int it = 0; it < 8; ++it) {
        const int node = (it << 2) + g;
        const float4* rowp = (const float4*)(hb + node * DIN);
        float p0 = 0.f, p1 = 0.f, p2 = 0.f;
        #pragma unroll
        for (int k = 0; k < 4; ++k) {
            float4 x  = rowp[q + (k << 3)];
            float4 v0 = *(const float4*)&g_v[0 * DIN + ((q + (k << 3)) << 2)];
            float4 v1 = *(const float4*)&g_v[1 * DIN + ((q + (k << 3)) << 2)];
            float4 v2 = *(const float4*)&g_v[2 * DIN + ((q + (k << 3)) << 2)];
            p0 += dot4(x, v0); p1 += dot4(x, v1); p2 += dot4(x, v2);
        }
        #pragma unroll
        for (int o = 4; o; o >>= 1) {
            p0 += __shfl_xor_sync(0xffffffffu, p0, o);
            p1 += __shfl_xor_sync(0xffffffffu, p1, o);
            p2 += __shfl_xor_sync(0xffffffffu, p2, o);
        }
        if (q == 0) {
            snb[0 * 32 + node] = p0;
            snb[1 * 32 + node] = p1;
            snb[2 * 32 + node] = p2;
        }
    }

    // ---- s_self: 9 u-dots on node-0 row (warp-uniform loop shape) ----
    {
        float4 x0[4];
        #pragma unroll
        for (int k = 0; k < 4; ++k)
            x0[k] = ((const float4*)hb)[q + (k << 3)];   // node-0 row
        #pragma unroll
        for (int t = 0; t < 3; ++t) {
            int ui = g * 3 + t; if (ui > 8) ui = 8;      // groups 2/3 dup ui=8 (benign)
            const float* uvec = g_u + ui * DIN;
            float p = 0.f;
            #pragma unroll
            for (int k = 0; k < 4; ++k)
                p += dot4(x0[k], *(const float4*)&uvec[(q + (k << 3)) << 2]);
            #pragma unroll
            for (int o = 4; o; o >>= 1) p += __shfl_xor_sync(0xffffffffu, p, o);
            if (q == 0) sss[ui] = p;
        }
    }
    __syncwarp();

    // ---- dual register-resident softmax (lanes 1..15 ally, 16..31 opp) ----
    const float r0 = snb[0 * 32 + lane];
    const float r1 = snb[1 * 32 + lane];
    const float r2 = snb[2 * 32 + lane];
    float ss[9];
    #pragma unroll
    for (int k = 0; k < 9; ++k) ss[k] = sss[k];

    const float eb0 = (m0 || lane == 0) ? -INFINITY : r0;
    const float eb1 = (m1 || lane == 0) ? -INFINITY : r1;
    const float eb2 = (m2 || lane == 0) ? -INFINITY : r2;

    float mx = -INFINITY;
    #pragma unroll
    for (int i = 0; i < 3; ++i) {
        mx = fmaxf(mx, ss[i * 3 + 0] + eb0);
        mx = fmaxf(mx, ss[i * 3 + 1] + eb1);
        mx = fmaxf(mx, ss[i * 3 + 2] + eb2);
    }
    #pragma unroll
    for (int o = 8; o; o >>= 1) mx = fmaxf(mx, __shfl_xor_sync(0xffffffffu, mx, o));

    float s0 = 0.f, s1 = 0.f, s2 = 0.f;
    #pragma unroll
    for (int i = 0; i < 3; ++i) {
        s0 += __expf(ss[i * 3 + 0] + eb0 - mx);
        s1 += __expf(ss[i * 3 + 1] + eb1 - mx);
        s2 += __expf(ss[i * 3 + 2] + eb2 - mx);
    }
    float zs = s0 + s1 + s2;
    #pragma unroll
    for (int o = 8; o; o >>= 1) zs += __shfl_xor_sync(0xffffffffu, zs, o);
    // all-masked half -> zs NaN -> inv 0 -> weights 0 (matches reference)
    const float inv = (zs > 0.f) ? (1.f / zs) : 0.f;

    swt[0 * 32 + lane] = (lane == 0) ? (m0 ? 1.f : 0.f) : s0 * inv;
    swt[1 * 32 + lane] = (lane == 0) ? (m1 ? 1.f : 0.f) : s1 * inv;
    swt[2 * 32 + lane] = (lane == 0) ? (m2 ? 1.f : 0.f) : s2 * inv;
    __syncwarp();

    // ---- combine: re-read h (L1/L2 hot), coalesced, FMA into 3 accs ----
    const float4* hv = (const float4*)hb;
    float4 a0 = {0.f, 0.f, 0.f, 0.f}, a1 = a0, a2 = a0;
    #pragma unroll
    for (int n = 0; n < NNODES; ++n) {
        float4 x = hv[(n << 5) + lane];
        float w0 = swt[n], w1 = swt[32 + n], w2 = swt[64 + n];
        a0.x += w0 * x.x; a0.y += w0 * x.y; a0.z += w0 * x.z; a0.w += w0 * x.w;
        a1.x += w1 * x.x; a1.y += w1 * x.y; a1.z += w1 * x.z; a1.w += w1 * x.w;
        a2.x += w2 * x.x; a2.y += w2 * x.y; a2.z += w2 * x.z; a2.w += w2 * x.w;
    }
    float* gout = g_C + (size_t)b * (TT * DIN);
    const int d4 = lane << 2;
    *(float4*)&gout[0 * DIN + d4] = a0;
    *(float4*)&gout[1 * DIN + d4] = a1;
    *(float4*)&gout[2 * DIN + d4] = a2;
}

// ---------------------------------------------------------------------------
// k2: out = elu(C @ Wstack). M=8192, K=384, N=128. fp32 packed FFMA2.
// BM=BN=BK=64; block=256; grid=(128,2) -> all 256 CTAs resident in one wave.
// CTA (0,0) resets g_done for the next graph replay.
// ---------------------------------------------------------------------------
#define GBM 64
#define GBN 64
#define GBK 64
#define APAD 3

#define FMA_F32X2(d, a, bb, c) \
    asm("fma.rn.f32x2 %0, %1, %2, %3;" : "=l"(d) : "l"(a), "l"(bb), "l"(c))
#define PACK_DUP(d, s) \
    asm("mov.b64 %0, {%1, %1};" : "=l"(d) : "r"(s))

__global__ __launch_bounds__(256) void k2_gemm_elu(
    const float* __restrict__ W, float* __restrict__ out)
{
    __shared__ float As[GBK][GBM + APAD];   // [k][m]
    __shared__ float Bs[GBK][GBN];          // [k][n]

    if (blockIdx.x == 0 && blockIdx.y == 0 && threadIdx.x == 0)
        g_done = 0u;                        // reset for next launch (stream-ordered)

    const int tid = threadIdx.x;
    const int bm0 = blockIdx.x * GBM;
    const int bn0 = blockIdx.y * GBN;
    const int tm0 = tid & 31;               // m = tm0 + 32*mi
    const int tn  = (tid >> 5) << 3;        // warp-uniform, 0..56

    unsigned long long acc[2][4];
    #pragma unroll
    for (int i = 0; i < 2; ++i)
        #pragma unroll
        for (int j = 0; j < 4; ++j) acc[i][j] = 0ull;

    const float* A = g_C;

    for (int k0 = 0; k0 < TT * DIN; k0 += GBK) {
        #pragma unroll
        for (int i = 0; i < 4; ++i) {       // A tile 64x64 -> transpose to As[k][m]
            int li = tid + i * 256;
            int r  = li >> 4;
            int c4 = (li & 15) << 2;
            float4 v = *(const float4*)&A[(size_t)(bm0 + r) * (TT * DIN) + k0 + c4];
            As[c4 + 0][r] = v.x; As[c4 + 1][r] = v.y;
            As[c4 + 2][r] = v.z; As[c4 + 3][r] = v.w;
        }
        #pragma unroll
        for (int i = 0; i < 4; ++i) {       // B tile 64x64 natural
            int li = tid + i * 256;
            int r  = li >> 4;
            int c4 = (li & 15) << 2;
            *(float4*)&Bs[r][c4] = *(const float4*)&W[(size_t)(k0 + r) * DIN + bn0 + c4];
        }
        __syncthreads();

        #pragma unroll 8
        for (int kk = 0; kk < GBK; ++kk) {
            unsigned long long ad[2];
            PACK_DUP(ad[0], __float_as_uint(As[kk][tm0]));
            PACK_DUP(ad[1], __float_as_uint(As[kk][tm0 + 32]));
            ulonglong2 b01 = *(const ulonglong2*)&Bs[kk][tn];
            ulonglong2 b23 = *(const ulonglong2*)&Bs[kk][tn + 4];
            unsigned long long bv[4] = {b01.x, b01.y, b23.x, b23.y};
            #pragma unroll
            for (int mi = 0; mi < 2; ++mi)
                #pragma unroll
                for (int jj = 0; jj < 4; ++jj)
                    FMA_F32X2(acc[mi][jj], ad[mi], bv[jj], acc[mi][jj]);
        }
        __syncthreads();
    }

    #pragma unroll
    for (int mi = 0; mi < 2; ++mi) {
        int m = bm0 + tm0 + 32 * mi;
        float o8[8];
        #pragma unroll
        for (int jj = 0; jj < 4; ++jj) {
            unsigned long long p = acc[mi][jj];
            o8[2 * jj]     = __uint_as_float((unsigned)(p & 0xffffffffull));
            o8[2 * jj + 1] = __uint_as_float((unsigned)(p >> 32));
        }
        #pragma unroll
        for (int q = 0; q < 8; ++q) {
            float x = o8[q];
            o8[q] = x > 0.f ? x : expm1f(x);
        }
        *(float4*)&out[(size_t)m * DIN + bn0 + tn]     = *(float4*)&o8[0];
        *(float4*)&out[(size_t)m * DIN + bn0 + tn + 4] = *(float4*)&o8[4];
    }
}

// ---------------------------------------------------------------------------
extern "C" void kernel_launch(void* const* d_in, const int* in_sizes, int n_in,
                              void* d_out, int out_size)
{
    const float* h = nullptr;
    const void*  mask = nullptr;
    const float* W = nullptr;
    const float* a = nullptr;

    for (int i = 0; i < n_in; ++i) {
        switch (in_sizes[i]) {
            case BATCH * NNODES * DIN: h    = (const float*)d_in[i]; break;   // 33554432
            case TT * BATCH * NNODES:  mask = d_in[i];               break;   // 786432
            case TT * DIN * HID:       W    = (const float*)d_in[i]; break;   // 49152
            case TT * 2 * HID:         a    = (const float*)d_in[i]; break;   // 768
            default: break; // scalars
        }
    }

    k1_fused<<<BATCH / K1_WARPS, 32 * K1_WARPS>>>(h, mask, W, a);
    k2_gemm_elu<<<dim3(BATCH / GBM, DIN / GBN), 256>>>(W, (float*)d_out);
}

// round 12
// speedup vs baseline: 1.1838x; 1.1838x over previous
#include <cuda_runtime.h>
#include <cstdint>
#include <math.h>

// Problem constants
#define BATCH   8192
#define NNODES  32
#define DIN     128
#define HID     128
#define TT      3

// Scratch (__device__ globals; cudaMalloc is forbidden)
__device__ float g_C[BATCH * TT * DIN];   // combined vectors (b, j*128+d)
__device__ float g_u[9 * DIN];            // u[i*3+j][d] = sum_h W[i][d][h]*a_top[j][h]
__device__ float g_v[TT * DIN];           // v[j][d]     = sum_h W[j][d][h]*a_bot[j][h]
__device__ unsigned g_det;                // mask dtype classification bits

// ---------------------------------------------------------------------------
// Mask dtype helpers (bool buffer may be u8 / i32 / f32 on device).
// ---------------------------------------------------------------------------
__device__ __forceinline__ int mask_mode_from_det(unsigned d)
{
    if (!(d & 1u)) return 1;   // int32
    if (!(d & 2u)) return 2;   // float32
    return 0;                  // uint8
}
__device__ __forceinline__ bool mask_at(const void* m, size_t idx, int mode)
{
    if (mode == 0) return ((const unsigned char*)m)[idx] != 0;
    if (mode == 1) return ((const int*)m)[idx] != 0;
    return ((const float*)m)[idx] != 0.f;
}

__device__ __forceinline__ float dot4(float4 x, float4 y)
{ return x.x * y.x + x.y * y.y + x.z * y.z + x.w * y.w; }

// ---------------------------------------------------------------------------
// k0: 8 dots per warp (MLP=8). 1536 dots -> 192 warps -> 24 blocks x 256.
// Block 24 does mask dtype detection.
// ---------------------------------------------------------------------------
__global__ __launch_bounds__(256) void k0_precompute(
    const float* __restrict__ W, const float* __restrict__ a,
    const unsigned* __restrict__ mraw)
{
    if (blockIdx.x == 24) {   // detection: scan first 8KB (2048 words)
        __shared__ unsigned sacc;
        int t = threadIdx.x;
        if (t == 0) sacc = 0u;
        __syncthreads();
        unsigned local = 0;
        for (int i = t; i < 2048; i += 256) {
            unsigned w = mraw[i];
            if (w > 1u) local |= 1u;
            if (w != 0u && w != 0x3F800000u) local |= 2u;
        }
        if (local) atomicOr(&sacc, local);
        __syncthreads();
        if (t == 0) g_det = sacc;
        return;
    }
    const int lane = threadIdx.x & 31;
    const int wg   = blockIdx.x * 8 + (threadIdx.x >> 5);   // 0..191
    const int base = wg * 8;                                // dot ids base..base+7
    const int vb   = base >> 7;                             // 0..11 (const across 8)
    const int d0   = base & 127;

    const float* Wbase;
    const float* avec;
    if (vb < 9) {
        Wbase = W + (size_t)(vb / 3) * (DIN * HID);
        avec  = a + (vb % 3) * (2 * HID);
    } else {
        Wbase = W + (size_t)(vb - 9) * (DIN * HID);
        avec  = a + (vb - 9) * (2 * HID) + HID;
    }
    float4 av = *(const float4*)&avec[lane << 2];

    float acc[8];
    #pragma unroll
    for (int r = 0; r < 8; ++r) {
        float4 wv = *(const float4*)&Wbase[(size_t)(d0 + r) * HID + (lane << 2)];
        acc[r] = dot4(wv, av);
    }
    #pragma unroll
    for (int o = 16; o; o >>= 1)
        #pragma unroll
        for (int r = 0; r < 8; ++r)
            acc[r] += __shfl_xor_sync(0xffffffffu, acc[r], o);
    if (lane == 0) {
        float4 lo = {acc[0], acc[1], acc[2], acc[3]};
        float4 hi = {acc[4], acc[5], acc[6], acc[7]};
        if (vb < 9) {
            *(float4*)&g_u[vb * DIN + d0]     = lo;
            *(float4*)&g_u[vb * DIN + d0 + 4] = hi;
        } else {
            *(float4*)&g_v[(vb - 9) * DIN + d0]     = lo;
            *(float4*)&g_v[(vb - 9) * DIN + d0 + 4] = hi;
        }
    }
}

// ---------------------------------------------------------------------------
// k1-lite (round-9 proven config): one WARP per batch, ~900B smem/warp.
// Dot phase: 8-lane groups own quarter-rows, 4 nodes per warp-iteration,
// coalesced loads, 3-stage group butterflies. Combine re-reads h (L1/L2 hot).
// 8 warps/CTA, grid=1024, __launch_bounds__(256,3) -> 24 warps/SM.
// ---------------------------------------------------------------------------
#define K1_WARPS 8
#define WSL      224   // per-warp smem floats: nb[3][32] + ss[16] + wt[3][32] + pad

__global__ __launch_bounds__(256, 3) void k1_scores_combine(
    const float* __restrict__ h, const void* __restrict__ mask)
{
    __shared__ float smem[K1_WARPS * WSL];
    const int lane = threadIdx.x & 31;
    const int w    = threadIdx.x >> 5;
    const int b    = blockIdx.x * K1_WARPS + w;
    const int mode = mask_mode_from_det(g_det);
    float* snb = smem + w * WSL;     // [3][32] neighbor scores
    float* sss = snb + 96;           // [9] self scores (+pad)
    float* swt = sss + 16;           // [3][32] weights

    const int g = lane >> 3;         // group 0..3 (node within 4-pack)
    const int q = lane & 7;          // quarter position 0..7

    const float* hb = h + (size_t)b * NNODES * DIN;

    // ---- masks early (hide latency under dot phase) ----
    const size_t mstr = (size_t)BATCH * NNODES;
    const size_t mb   = (size_t)b * NNODES + lane;
    const bool m0 = mask_at(mask, 0 * mstr + mb, mode);
    const bool m1 = mask_at(mask, 1 * mstr + mb, mode);
    const bool m2 = mask_at(mask, 2 * mstr + mb, mode);

    // ---- dot phase: 8 iterations x 4 nodes ----
    #pragma unroll
    for (int it = 0; it < 8; ++it) {
        const int node = (it << 2) + g;
        const float4* rowp = (const float4*)(hb + node * DIN);
        float p0 = 0.f, p1 = 0.f, p2 = 0.f;
        #pragma unroll
        for (int k = 0; k < 4; ++k) {
            float4 x  = rowp[q + (k << 3)];
            float4 v0 = *(const float4*)&g_v[0 * DIN + ((q + (k << 3)) << 2)];
            float4 v1 = *(const float4*)&g_v[1 * DIN + ((q + (k << 3)) << 2)];
            float4 v2 = *(const float4*)&g_v[2 * DIN + ((q + (k << 3)) << 2)];
            p0 += dot4(x, v0); p1 += dot4(x, v1); p2 += dot4(x, v2);
        }
        #pragma unroll
        for (int o = 4; o; o >>= 1) {
            p0 += __shfl_xor_sync(0xffffffffu, p0, o);
            p1 += __shfl_xor_sync(0xffffffffu, p1, o);
            p2 += __shfl_xor_sync(0xffffffffu, p2, o);
        }
        if (q == 0) {
            snb[0 * 32 + node] = p0;
            snb[1 * 32 + node] = p1;
            snb[2 * 32 + node] = p2;
        }
    }

    // ---- s_self: 9 u-dots on node-0 row (warp-uniform loop shape) ----
    {
        float4 x0[4];
        #pragma unroll
        for (int k = 0; k < 4; ++k)
            x0[k] = ((const float4*)hb)[q + (k << 3)];   // node-0 row
        #pragma unroll
        for (int t = 0; t < 3; ++t) {
            int ui = g * 3 + t; if (ui > 8) ui = 8;      // groups 2/3 dup ui=8 (benign)
            const float* uvec = g_u + ui * DIN;
            float p = 0.f;
            #pragma unroll
            for (int k = 0; k < 4; ++k)
                p += dot4(x0[k], *(const float4*)&uvec[(q + (k << 3)) << 2]);
            #pragma unroll
            for (int o = 4; o; o >>= 1) p += __shfl_xor_sync(0xffffffffu, p, o);
            if (q == 0) sss[ui] = p;
        }
    }
    __syncwarp();

    // ---- dual register-resident softmax (lanes 1..15 ally, 16..31 opp) ----
    const float r0 = snb[0 * 32 + lane];
    const float r1 = snb[1 * 32 + lane];
    const float r2 = snb[2 * 32 + lane];
    float ss[9];
    #pragma unroll
    for (int k = 0; k < 9; ++k) ss[k] = sss[k];

    const float eb0 = (m0 || lane == 0) ? -INFINITY : r0;
    const float eb1 = (m1 || lane == 0) ? -INFINITY : r1;
    const float eb2 = (m2 || lane == 0) ? -INFINITY : r2;

    float mx = -INFINITY;
    #pragma unroll
    for (int i = 0; i < 3; ++i) {
        mx = fmaxf(mx, ss[i * 3 + 0] + eb0);
        mx = fmaxf(mx, ss[i * 3 + 1] + eb1);
        mx = fmaxf(mx, ss[i * 3 + 2] + eb2);
    }
    #pragma unroll
    for (int o = 8; o; o >>= 1) mx = fmaxf(mx, __shfl_xor_sync(0xffffffffu, mx, o));

    float s0 = 0.f, s1 = 0.f, s2 = 0.f;
    #pragma unroll
    for (int i = 0; i < 3; ++i) {
        s0 += __expf(ss[i * 3 + 0] + eb0 - mx);
        s1 += __expf(ss[i * 3 + 1] + eb1 - mx);
        s2 += __expf(ss[i * 3 + 2] + eb2 - mx);
    }
    float zs = s0 + s1 + s2;
    #pragma unroll
    for (int o = 8; o; o >>= 1) zs += __shfl_xor_sync(0xffffffffu, zs, o);
    // all-masked half -> zs NaN -> inv 0 -> weights 0 (matches reference)
    const float inv = (zs > 0.f) ? (1.f / zs) : 0.f;

    swt[0 * 32 + lane] = (lane == 0) ? (m0 ? 1.f : 0.f) : s0 * inv;
    swt[1 * 32 + lane] = (lane == 0) ? (m1 ? 1.f : 0.f) : s1 * inv;
    swt[2 * 32 + lane] = (lane == 0) ? (m2 ? 1.f : 0.f) : s2 * inv;
    __syncwarp();

    // ---- combine: re-read h (L1/L2 hot), coalesced, FMA into 3 accs ----
    const float4* hv = (const float4*)hb;
    float4 a0 = {0.f, 0.f, 0.f, 0.f}, a1 = a0, a2 = a0;
    #pragma unroll
    for (int n = 0; n < NNODES; ++n) {
        float4 x = hv[(n << 5) + lane];
        float w0 = swt[n], w1 = swt[32 + n], w2 = swt[64 + n];
        a0.x += w0 * x.x; a0.y += w0 * x.y; a0.z += w0 * x.z; a0.w += w0 * x.w;
        a1.x += w1 * x.x; a1.y += w1 * x.y; a1.z += w1 * x.z; a1.w += w1 * x.w;
        a2.x += w2 * x.x; a2.y += w2 * x.y; a2.z += w2 * x.z; a2.w += w2 * x.w;
    }
    float* gout = g_C + (size_t)b * (TT * DIN);
    const int d4 = lane << 2;
    *(float4*)&gout[0 * DIN + d4] = a0;
    *(float4*)&gout[1 * DIN + d4] = a1;
    *(float4*)&gout[2 * DIN + d4] = a2;
}

// ---------------------------------------------------------------------------
// k2: out = elu(C @ Wstack). M=8192, K=384, N=128. fp32 packed FFMA2.
// BM=32, BN=64, BK=64; block=256; grid=(256,2)=512 CTAs (~3.5/SM).
// Per-thread 1(M)x8(N).
// ---------------------------------------------------------------------------
#define GBM 32
#define GBN 64
#define GBK 64
#define APAD 1

#define FMA_F32X2(d, a, bb, c) \
    asm("fma.rn.f32x2 %0, %1, %2, %3;" : "=l"(d) : "l"(a), "l"(bb), "l"(c))
#define PACK_DUP(d, s) \
    asm("mov.b64 %0, {%1, %1};" : "=l"(d) : "r"(s))

__global__ __launch_bounds__(256) void k2_gemm_elu(
    const float* __restrict__ W, float* __restrict__ out)
{
    __shared__ float As[GBK][GBM + APAD];   // [k][m]
    __shared__ float Bs[GBK][GBN];          // [k][n]

    const int tid = threadIdx.x;
    const int bm0 = blockIdx.x * GBM;
    const int bn0 = blockIdx.y * GBN;
    const int tm0 = tid & 31;               // m row 0..31
    const int tn  = (tid >> 5) << 3;        // warp-uniform, 0..56

    unsigned long long acc[4];              // 4 n-pairs = 8 outputs
    #pragma unroll
    for (int j = 0; j < 4; ++j) acc[j] = 0ull;

    const float* A = g_C;

    for (int k0 = 0; k0 < TT * DIN; k0 += GBK) {
        #pragma unroll
        for (int i = 0; i < 2; ++i) {       // A tile 32x64 -> transpose to As[k][m]
            int li = tid + i * 256;         // 0..511
            int r  = li >> 4;               // m row 0..31
            int c4 = (li & 15) << 2;        // k col 0..60
            float4 v = *(const float4*)&A[(size_t)(bm0 + r) * (TT * DIN) + k0 + c4];
            As[c4 + 0][r] = v.x; As[c4 + 1][r] = v.y;
            As[c4 + 2][r] = v.z; As[c4 + 3][r] = v.w;
        }
        #pragma unroll
        for (int i = 0; i < 4; ++i) {       // B tile 64x64 natural
            int li = tid + i * 256;
            int r  = li >> 4;               // k row 0..63
            int c4 = (li & 15) << 2;        // n col 0..60
            *(float4*)&Bs[r][c4] = *(const float4*)&W[(size_t)(k0 + r) * DIN + bn0 + c4];
        }
        __syncthreads();

        #pragma unroll 8
        for (int kk = 0; kk < GBK; ++kk) {
            unsigned long long ad;
            PACK_DUP(ad, __float_as_uint(As[kk][tm0]));
            ulonglong2 b01 = *(const ulonglong2*)&Bs[kk][tn];      // warp-broadcast
            ulonglong2 b23 = *(const ulonglong2*)&Bs[kk][tn + 4];
            FMA_F32X2(acc[0], ad, b01.x, acc[0]);
            FMA_F32X2(acc[1], ad, b01.y, acc[1]);
            FMA_F32X2(acc[2], ad, b23.x, acc[2]);
            FMA_F32X2(acc[3], ad, b23.y, acc[3]);
        }
        __syncthreads();
    }

    // epilogue: unpack, ELU, store
    {
        int m = bm0 + tm0;
        float o8[8];
        #pragma unroll
        for (int jj = 0; jj < 4; ++jj) {
            unsigned long long p = acc[jj];
            o8[2 * jj]     = __uint_as_float((unsigned)(p & 0xffffffffull));
            o8[2 * jj + 1] = __uint_as_float((unsigned)(p >> 32));
        }
        #pragma unroll
        for (int q = 0; q < 8; ++q) {
            float x = o8[q];
            o8[q] = x > 0.f ? x : expm1f(x);
        }
        *(float4*)&out[(size_t)m * DIN + bn0 + tn]     = *(float4*)&o8[0];
        *(float4*)&out[(size_t)m * DIN + bn0 + tn + 4] = *(float4*)&o8[4];
    }
}

// ---------------------------------------------------------------------------
extern "C" void kernel_launch(void* const* d_in, const int* in_sizes, int n_in,
                              void* d_out, int out_size)
{
    const float* h = nullptr;
    const void*  mask = nullptr;
    const float* W = nullptr;
    const float* a = nullptr;

    for (int i = 0; i < n_in; ++i) {
        switch (in_sizes[i]) {
            case BATCH * NNODES * DIN: h    = (const float*)d_in[i]; break;   // 33554432
            case TT * BATCH * NNODES:  mask = d_in[i];               break;   // 786432
            case TT * DIN * HID:       W    = (const float*)d_in[i]; break;   // 49152
            case TT * 2 * HID:         a    = (const float*)d_in[i]; break;   // 768
            default: break; // scalars
        }
    }

    k0_precompute<<<25, 256>>>(W, a, (const unsigned*)mask);
    k1_scores_combine<<<BATCH / K1_WARPS, 32 * K1_WARPS>>>(h, mask);
    k2_gemm_elu<<<dim3(BATCH / GBM, DIN / GBN), 256>>>(W, (float*)d_out);
}

// round 13
// speedup vs baseline: 1.3304x; 1.1238x over previous
#include <cuda_runtime.h>
#include <cstdint>
#include <math.h>

// Problem constants
#define BATCH   8192
#define NNODES  32
#define DIN     128
#define HID     128
#define TT      3

// Scratch (__device__ globals; cudaMalloc is forbidden)
__device__ float g_C[BATCH * TT * DIN];   // combined vectors (b, j*128+d)
__device__ float g_u[9 * DIN];            // u[i*3+j][d] = sum_h W[i][d][h]*a_top[j][h]
__device__ float g_v[TT * DIN];           // v[j][d]     = sum_h W[j][d][h]*a_bot[j][h]
__device__ unsigned g_det;                // mask dtype classification bits

// ---------------------------------------------------------------------------
// Mask dtype helpers (bool buffer may be u8 / i32 / f32 on device).
// ---------------------------------------------------------------------------
__device__ __forceinline__ int mask_mode_from_det(unsigned d)
{
    if (!(d & 1u)) return 1;   // int32
    if (!(d & 2u)) return 2;   // float32
    return 0;                  // uint8
}
__device__ __forceinline__ bool mask_at(const void* m, size_t idx, int mode)
{
    if (mode == 0) return ((const unsigned char*)m)[idx] != 0;
    if (mode == 1) return ((const int*)m)[idx] != 0;
    return ((const float*)m)[idx] != 0.f;
}

__device__ __forceinline__ float dot4(float4 x, float4 y)
{ return x.x * y.x + x.y * y.y + x.z * y.z + x.w * y.w; }

// ---------------------------------------------------------------------------
// k0: 8 dots per warp (MLP=8). 1536 dots -> 192 warps -> 24 blocks x 256.
// Block 24 does mask dtype detection.
// ---------------------------------------------------------------------------
__global__ __launch_bounds__(256) void k0_precompute(
    const float* __restrict__ W, const float* __restrict__ a,
    const unsigned* __restrict__ mraw)
{
    if (blockIdx.x == 24) {   // detection: scan first 8KB (2048 words)
        __shared__ unsigned sacc;
        int t = threadIdx.x;
        if (t == 0) sacc = 0u;
        __syncthreads();
        unsigned local = 0;
        for (int i = t; i < 2048; i += 256) {
            unsigned w = mraw[i];
            if (w > 1u) local |= 1u;
            if (w != 0u && w != 0x3F800000u) local |= 2u;
        }
        if (local) atomicOr(&sacc, local);
        __syncthreads();
        if (t == 0) g_det = sacc;
        return;
    }
    const int lane = threadIdx.x & 31;
    const int wg   = blockIdx.x * 8 + (threadIdx.x >> 5);   // 0..191
    const int base = wg * 8;                                // dot ids base..base+7
    const int vb   = base >> 7;                             // 0..11 (const across 8)
    const int d0   = base & 127;

    const float* Wbase;
    const float* avec;
    if (vb < 9) {
        Wbase = W + (size_t)(vb / 3) * (DIN * HID);
        avec  = a + (vb % 3) * (2 * HID);
    } else {
        Wbase = W + (size_t)(vb - 9) * (DIN * HID);
        avec  = a + (vb - 9) * (2 * HID) + HID;
    }
    float4 av = *(const float4*)&avec[lane << 2];

    float acc[8];
    #pragma unroll
    for (int r = 0; r < 8; ++r) {
        float4 wv = *(const float4*)&Wbase[(size_t)(d0 + r) * HID + (lane << 2)];
        acc[r] = dot4(wv, av);
    }
    #pragma unroll
    for (int o = 16; o; o >>= 1)
        #pragma unroll
        for (int r = 0; r < 8; ++r)
            acc[r] += __shfl_xor_sync(0xffffffffu, acc[r], o);
    if (lane == 0) {
        float4 lo = {acc[0], acc[1], acc[2], acc[3]};
        float4 hi = {acc[4], acc[5], acc[6], acc[7]};
        if (vb < 9) {
            *(float4*)&g_u[vb * DIN + d0]     = lo;
            *(float4*)&g_u[vb * DIN + d0 + 4] = hi;
        } else {
            *(float4*)&g_v[(vb - 9) * DIN + d0]     = lo;
            *(float4*)&g_v[(vb - 9) * DIN + d0 + 4] = hi;
        }
    }
}

// ---------------------------------------------------------------------------
// k1-lite (round-9 proven config, unchanged): one WARP per batch.
// ---------------------------------------------------------------------------
#define K1_WARPS 8
#define WSL      224   // per-warp smem floats: nb[3][32] + ss[16] + wt[3][32] + pad

__global__ __launch_bounds__(256, 3) void k1_scores_combine(
    const float* __restrict__ h, const void* __restrict__ mask)
{
    __shared__ float smem[K1_WARPS * WSL];
    const int lane = threadIdx.x & 31;
    const int w    = threadIdx.x >> 5;
    const int b    = blockIdx.x * K1_WARPS + w;
    const int mode = mask_mode_from_det(g_det);
    float* snb = smem + w * WSL;     // [3][32] neighbor scores
    float* sss = snb + 96;           // [9] self scores (+pad)
    float* swt = sss + 16;           // [3][32] weights

    const int g = lane >> 3;         // group 0..3 (node within 4-pack)
    const int q = lane & 7;          // quarter position 0..7

    const float* hb = h + (size_t)b * NNODES * DIN;

    // ---- masks early (hide latency under dot phase) ----
    const size_t mstr = (size_t)BATCH * NNODES;
    const size_t mb   = (size_t)b * NNODES + lane;
    const bool m0 = mask_at(mask, 0 * mstr + mb, mode);
    const bool m1 = mask_at(mask, 1 * mstr + mb, mode);
    const bool m2 = mask_at(mask, 2 * mstr + mb, mode);

    // ---- dot phase: 8 iterations x 4 nodes ----
    #pragma unroll
    for (int it = 0; it < 8; ++it) {
        const int node = (it << 2) + g;
        const float4* rowp = (const float4*)(hb + node * DIN);
        float p0 = 0.f, p1 = 0.f, p2 = 0.f;
        #pragma unroll
        for (int k = 0; k < 4; ++k) {
            float4 x  = rowp[q + (k << 3)];
            float4 v0 = *(const float4*)&g_v[0 * DIN + ((q + (k << 3)) << 2)];
            float4 v1 = *(const float4*)&g_v[1 * DIN + ((q + (k << 3)) << 2)];
            float4 v2 = *(const float4*)&g_v[2 * DIN + ((q + (k << 3)) << 2)];
            p0 += dot4(x, v0); p1 += dot4(x, v1); p2 += dot4(x, v2);
        }
        #pragma unroll
        for (int o = 4; o; o >>= 1) {
            p0 += __shfl_xor_sync(0xffffffffu, p0, o);
            p1 += __shfl_xor_sync(0xffffffffu, p1, o);
            p2 += __shfl_xor_sync(0xffffffffu, p2, o);
        }
        if (q == 0) {
            snb[0 * 32 + node] = p0;
            snb[1 * 32 + node] = p1;
            snb[2 * 32 + node] = p2;
        }
    }

    // ---- s_self: 9 u-dots on node-0 row (warp-uniform loop shape) ----
    {
        float4 x0[4];
        #pragma unroll
        for (int k = 0; k < 4; ++k)
            x0[k] = ((const float4*)hb)[q + (k << 3)];   // node-0 row
        #pragma unroll
        for (int t = 0; t < 3; ++t) {
            int ui = g * 3 + t; if (ui > 8) ui = 8;      // groups 2/3 dup ui=8 (benign)
            const float* uvec = g_u + ui * DIN;
            float p = 0.f;
            #pragma unroll
            for (int k = 0; k < 4; ++k)
                p += dot4(x0[k], *(const float4*)&uvec[(q + (k << 3)) << 2]);
            #pragma unroll
            for (int o = 4; o; o >>= 1) p += __shfl_xor_sync(0xffffffffu, p, o);
            if (q == 0) sss[ui] = p;
        }
    }
    __syncwarp();

    // ---- dual register-resident softmax (lanes 1..15 ally, 16..31 opp) ----
    const float r0 = snb[0 * 32 + lane];
    const float r1 = snb[1 * 32 + lane];
    const float r2 = snb[2 * 32 + lane];
    float ss[9];
    #pragma unroll
    for (int k = 0; k < 9; ++k) ss[k] = sss[k];

    const float eb0 = (m0 || lane == 0) ? -INFINITY : r0;
    const float eb1 = (m1 || lane == 0) ? -INFINITY : r1;
    const float eb2 = (m2 || lane == 0) ? -INFINITY : r2;

    float mx = -INFINITY;
    #pragma unroll
    for (int i = 0; i < 3; ++i) {
        mx = fmaxf(mx, ss[i * 3 + 0] + eb0);
        mx = fmaxf(mx, ss[i * 3 + 1] + eb1);
        mx = fmaxf(mx, ss[i * 3 + 2] + eb2);
    }
    #pragma unroll
    for (int o = 8; o; o >>= 1) mx = fmaxf(mx, __shfl_xor_sync(0xffffffffu, mx, o));

    float s0 = 0.f, s1 = 0.f, s2 = 0.f;
    #pragma unroll
    for (int i = 0; i < 3; ++i) {
        s0 += __expf(ss[i * 3 + 0] + eb0 - mx);
        s1 += __expf(ss[i * 3 + 1] + eb1 - mx);
        s2 += __expf(ss[i * 3 + 2] + eb2 - mx);
    }
    float zs = s0 + s1 + s2;
    #pragma unroll
    for (int o = 8; o; o >>= 1) zs += __shfl_xor_sync(0xffffffffu, zs, o);
    // all-masked half -> zs NaN -> inv 0 -> weights 0 (matches reference)
    const float inv = (zs > 0.f) ? (1.f / zs) : 0.f;

    swt[0 * 32 + lane] = (lane == 0) ? (m0 ? 1.f : 0.f) : s0 * inv;
    swt[1 * 32 + lane] = (lane == 0) ? (m1 ? 1.f : 0.f) : s1 * inv;
    swt[2 * 32 + lane] = (lane == 0) ? (m2 ? 1.f : 0.f) : s2 * inv;
    __syncwarp();

    // ---- combine: re-read h (L1/L2 hot), coalesced, FMA into 3 accs ----
    const float4* hv = (const float4*)hb;
    float4 a0 = {0.f, 0.f, 0.f, 0.f}, a1 = a0, a2 = a0;
    #pragma unroll
    for (int n = 0; n < NNODES; ++n) {
        float4 x = hv[(n << 5) + lane];
        float w0 = swt[n], w1 = swt[32 + n], w2 = swt[64 + n];
        a0.x += w0 * x.x; a0.y += w0 * x.y; a0.z += w0 * x.z; a0.w += w0 * x.w;
        a1.x += w1 * x.x; a1.y += w1 * x.y; a1.z += w1 * x.z; a1.w += w1 * x.w;
        a2.x += w2 * x.x; a2.y += w2 * x.y; a2.z += w2 * x.z; a2.w += w2 * x.w;
    }
    float* gout = g_C + (size_t)b * (TT * DIN);
    const int d4 = lane << 2;
    *(float4*)&gout[0 * DIN + d4] = a0;
    *(float4*)&gout[1 * DIN + d4] = a1;
    *(float4*)&gout[2 * DIN + d4] = a2;
}

// ---------------------------------------------------------------------------
// k2 v3: out = elu(C @ Wstack). M=8192, K=384, N=128. fp32 packed FFMA2.
// A stored ROW-MAJOR in smem (straight copy; 1 LDS.128 = 4 k-values of A).
// BM=64, BN=32, BK=64; block=256; grid=(128,4)=512 CTAs (~3.5/SM, 28 warps).
// Per-thread 2(M)x4(N); per 4k: 6 LDS.128 + 8 pack + 16 FMA2 (0.375 LDS/FMA2).
// ---------------------------------------------------------------------------
#define GBM 64
#define GBN 32
#define GBK 64
#define AST (GBK + 4)   // As row stride 68 floats: stride%32=4 -> LDS.128 conflict-free

#define FMA_F32X2(d, a, bb, c) \
    asm("fma.rn.f32x2 %0, %1, %2, %3;" : "=l"(d) : "l"(a), "l"(bb), "l"(c))
#define PACK_DUP(d, s) \
    asm("mov.b64 %0, {%1, %1};" : "=l"(d) : "r"(s))

__global__ __launch_bounds__(256) void k2_gemm_elu(
    const float* __restrict__ W, float* __restrict__ out)
{
    __shared__ float As[GBM][AST];   // [m][k] row-major
    __shared__ float Bs[GBK][GBN];   // [k][n]

    const int tid = threadIdx.x;
    const int bm0 = blockIdx.x * GBM;
    const int bn0 = blockIdx.y * GBN;
    const int tm0 = tid & 31;               // m = tm0 + 32*mi
    const int tn  = (tid >> 5) << 2;        // warp-uniform, 0..28

    unsigned long long acc[2][2];           // [mi][n-pair]
    acc[0][0] = acc[0][1] = acc[1][0] = acc[1][1] = 0ull;

    const float* A = g_C;

    for (int k0 = 0; k0 < TT * DIN; k0 += GBK) {
        // A tile 64x64: straight row-major copy, 4 float4 per thread
        #pragma unroll
        for (int i = 0; i < 4; ++i) {
            int li = tid + i * 256;
            int r  = li >> 4;                // m row 0..63
            int c4 = (li & 15) << 2;         // k col 0..60
            *(float4*)&As[r][c4] =
                *(const float4*)&A[(size_t)(bm0 + r) * (TT * DIN) + k0 + c4];
        }
        // B tile 64x32: 2 float4 per thread
        #pragma unroll
        for (int i = 0; i < 2; ++i) {
            int li = tid + i * 256;
            int r  = li >> 3;                // k row 0..63
            int c4 = (li & 7) << 2;          // n col 0..28
            *(float4*)&Bs[r][c4] = *(const float4*)&W[(size_t)(k0 + r) * DIN + bn0 + c4];
        }
        __syncthreads();

        #pragma unroll
        for (int kb = 0; kb < GBK; kb += 4) {
            float4 af0 = *(const float4*)&As[tm0][kb];
            float4 af1 = *(const float4*)&As[tm0 + 32][kb];
            float a0v[4] = {af0.x, af0.y, af0.z, af0.w};
            float a1v[4] = {af1.x, af1.y, af1.z, af1.w};
            #pragma unroll
            for (int kk = 0; kk < 4; ++kk) {
                ulonglong2 bb = *(const ulonglong2*)&Bs[kb + kk][tn];  // broadcast
                unsigned long long ad0, ad1;
                PACK_DUP(ad0, __float_as_uint(a0v[kk]));
                PACK_DUP(ad1, __float_as_uint(a1v[kk]));
                FMA_F32X2(acc[0][0], ad0, bb.x, acc[0][0]);
                FMA_F32X2(acc[0][1], ad0, bb.y, acc[0][1]);
                FMA_F32X2(acc[1][0], ad1, bb.x, acc[1][0]);
                FMA_F32X2(acc[1][1], ad1, bb.y, acc[1][1]);
            }
        }
        __syncthreads();
    }

    // epilogue: unpack, ELU, store
    #pragma unroll
    for (int mi = 0; mi < 2; ++mi) {
        int m = bm0 + tm0 + 32 * mi;
        float o4[4];
        #pragma unroll
        for (int jj = 0; jj < 2; ++jj) {
            unsigned long long p = acc[mi][jj];
            o4[2 * jj]     = __uint_as_float((unsigned)(p & 0xffffffffull));
            o4[2 * jj + 1] = __uint_as_float((unsigned)(p >> 32));
        }
        #pragma unroll
        for (int q = 0; q < 4; ++q) {
            float x = o4[q];
            o4[q] = x > 0.f ? x : expm1f(x);
        }
        *(float4*)&out[(size_t)m * DIN + bn0 + tn] = *(float4*)&o4[0];
    }
}

// ---------------------------------------------------------------------------
extern "C" void kernel_launch(void* const* d_in, const int* in_sizes, int n_in,
                              void* d_out, int out_size)
{
    const float* h = nullptr;
    const void*  mask = nullptr;
    const float* W = nullptr;
    const float* a = nullptr;

    for (int i = 0; i < n_in; ++i) {
        switch (in_sizes[i]) {
            case BATCH * NNODES * DIN: h    = (const float*)d_in[i]; break;   // 33554432
            case TT * BATCH * NNODES:  mask = d_in[i];               break;   // 786432
            case TT * DIN * HID:       W    = (const float*)d_in[i]; break;   // 49152
            case TT * 2 * HID:         a    = (const float*)d_in[i]; break;   // 768
            default: break; // scalars
        }
    }

    k0_precompute<<<25, 256>>>(W, a, (const unsigned*)mask);
    k1_scores_combine<<<BATCH / K1_WARPS, 32 * K1_WARPS>>>(h, mask);
    k2_gemm_elu<<<dim3(BATCH / GBM, DIN / GBN), 256>>>(W, (float*)d_out);
}